// round 4
// baseline (speedup 1.0000x reference)
#include <cuda_runtime.h>
#include <cuda_bf16.h>

// Zim_67430986547716 — bbox mask + separable-Gaussian point mask.
// R4: pack the main-loop multiplies with Blackwell mul.rn.f32x2.
//  - Row table stored DUPLICATED (r0,r0,r1,r1) so ld.shared.v2.u64 yields
//    ready-packed operands (no pack instructions).
//  - 4 packed muls + 8 FMNMX per point per thread: 14 issue slots vs 18.
//  - Unpacking via mov.b64 {lo,hi} is register-coalesced away by ptxas.

#define MASK_N 64
#define NPTS   32
#define ROWS_PER_BLOCK 32
#define INV_STRIDE (1.0f / 16.0f)
#define INV_2SIG2  (1.0f / 882.0f)   // 2*21*21

__device__ __forceinline__ unsigned long long mul_f32x2(unsigned long long a,
                                                        unsigned long long b) {
    unsigned long long r;
    asm("mul.rn.f32x2 %0, %1, %2;" : "=l"(r) : "l"(a), "l"(b));
    return r;
}

__device__ __forceinline__ void unpack2(unsigned long long v, float& lo, float& hi) {
    asm("mov.b64 {%0, %1}, %2;" : "=f"(lo), "=f"(hi) : "l"(v));
}

__device__ __forceinline__ unsigned long long pack2(float lo, float hi) {
    unsigned long long v;
    asm("mov.b64 %0, {%1, %2};" : "=l"(v) : "f"(lo), "f"(hi));
    return v;
}

__global__ __launch_bounds__(256, 4)
void zim_masks_kernel(const float* __restrict__ boxes,
                      const float* __restrict__ pts,
                      float* __restrict__ bbox_out,
                      float* __restrict__ point_out)
{
    __shared__ float gxs[NPTS * MASK_N];            // 8KB: [p][j] col Gaussian
    __shared__ float gysd[NPTS * ROWS_PER_BLOCK*2]; // 8KB: [p][2i],[2i+1] = row Gaussian DUPLICATED
    __shared__ float etab[128];                     // exp(-k^2/882)
    __shared__ int   spx[NPTS], spy[NPTS];
    __shared__ float sval[NPTS];

    const int b      = blockIdx.x;
    const int sub    = blockIdx.y;            // which 32-row half
    const int i_base = sub * ROWS_PER_BLOCK;
    const int tid    = threadIdx.x;

    // ---- exp LUT (128 MUFU/block) ----
    if (tid < 128) {
        const float d = (float)tid;
        etab[tid] = __expf(-d * d * INV_2SIG2);
    }
    // ---- stage point centers + validity ----
    if (tid >= 128 && tid < 128 + NPTS) {
        const int p = tid - 128;
        const float x = pts[(b * NPTS + p) * 2 + 0];
        const float y = pts[(b * NPTS + p) * 2 + 1];
        const int px = (int)floorf(x * INV_STRIDE);
        const int py = (int)floorf(y * INV_STRIDE);
        const bool valid = (px >= 0) & (py >= 0) & (px < MASK_N) & (py < MASK_N);
        spx[p] = px;
        spy[p] = py;
        sval[p] = valid ? 1.0f : 0.0f;
    }

    // ---- bbox bounds (uniform) ----
    const float x0 = boxes[b * 4 + 0];
    const float y0 = boxes[b * 4 + 1];
    const float x1 = boxes[b * 4 + 2];
    const float y1 = boxes[b * 4 + 3];
    const int xmin_i = max((int)floorf(fminf(x0, x1) * INV_STRIDE), 0);
    const int ymin_i = max((int)floorf(fminf(y0, y1) * INV_STRIDE), 0);
    const int xmax_i = min((int)floorf(fmaxf(x0, x1) * INV_STRIDE) + 1, MASK_N);
    const int ymax_i = min((int)floorf(fmaxf(y0, y1) * INV_STRIDE) + 1, MASK_N);

    __syncthreads();

    // ---- build tables via LUT ----
    #pragma unroll
    for (int idx = tid; idx < NPTS * MASK_N; idx += 256) {          // 8 iters: cols
        const int p = idx >> 6;
        int d = (idx & 63) - spx[p];
        d = min(abs(d), 127);
        gxs[idx] = sval[p] * etab[d];
    }
    #pragma unroll
    for (int idx = tid; idx < NPTS * ROWS_PER_BLOCK * 2; idx += 256) { // 8 iters: rows, duplicated
        const int p = idx >> 6;
        const int k = idx & 63;                 // duplicated index: row = k>>1
        int d = i_base + (k >> 1) - spy[p];
        d = min(abs(d), 127);
        gysd[idx] = sval[p] * etab[d];
    }
    __syncthreads();

    // ---- per-thread tile: 2 rows x 4 cols ----
    const int rg = tid >> 4;            // 0..15 -> local rows rg*2, rg*2+1
    const int il = rg << 1;
    const int c  = (tid & 15) << 2;     // col start

    float m0x = 0.f, m0y = 0.f, m0z = 0.f, m0w = 0.f;
    float m1x = 0.f, m1y = 0.f, m1z = 0.f, m1w = 0.f;

    const float* gyp = &gysd[il * 2];   // (r0,r0,r1,r1) at p-stride 64
    const float* gxp = &gxs[c];         // (g0..g3)      at p-stride 64

    #pragma unroll 8
    for (int p = 0; p < NPTS; p++) {
        const ulonglong2 ry = *reinterpret_cast<const ulonglong2*>(gyp + p * 64);
        const ulonglong2 gg = *reinterpret_cast<const ulonglong2*>(gxp + p * 64);
        // (r0,r0)*(g0,g1), (r0,r0)*(g2,g3), (r1,r1)*(g0,g1), (r1,r1)*(g2,g3)
        const unsigned long long a00 = mul_f32x2(ry.x, gg.x);
        const unsigned long long a01 = mul_f32x2(ry.x, gg.y);
        const unsigned long long a10 = mul_f32x2(ry.y, gg.x);
        const unsigned long long a11 = mul_f32x2(ry.y, gg.y);
        float t0, t1;
        unpack2(a00, t0, t1); m0x = fmaxf(m0x, t0); m0y = fmaxf(m0y, t1);
        unpack2(a01, t0, t1); m0z = fmaxf(m0z, t0); m0w = fmaxf(m0w, t1);
        unpack2(a10, t0, t1); m1x = fmaxf(m1x, t0); m1y = fmaxf(m1y, t1);
        unpack2(a11, t0, t1); m1z = fmaxf(m1z, t0); m1w = fmaxf(m1w, t1);
    }

    // ---- stores ----
    const int i0 = i_base + il;
    const size_t base0 = (size_t)b * (MASK_N * MASK_N) + (size_t)i0 * MASK_N + c;

    *reinterpret_cast<float4*>(point_out + base0)          = make_float4(m0x, m0y, m0z, m0w);
    *reinterpret_cast<float4*>(point_out + base0 + MASK_N) = make_float4(m1x, m1y, m1z, m1w);

    const bool inX0 = (c + 0 >= xmin_i) & (c + 0 < xmax_i);
    const bool inX1 = (c + 1 >= xmin_i) & (c + 1 < xmax_i);
    const bool inX2 = (c + 2 >= xmin_i) & (c + 2 < xmax_i);
    const bool inX3 = (c + 3 >= xmin_i) & (c + 3 < xmax_i);
    const bool inY0 = (i0 >= ymin_i) & (i0 < ymax_i);
    const bool inY1 = (i0 + 1 >= ymin_i) & (i0 + 1 < ymax_i);

    *reinterpret_cast<float4*>(bbox_out + base0) =
        make_float4((inY0 & inX0) ? 1.f : 0.f, (inY0 & inX1) ? 1.f : 0.f,
                    (inY0 & inX2) ? 1.f : 0.f, (inY0 & inX3) ? 1.f : 0.f);
    *reinterpret_cast<float4*>(bbox_out + base0 + MASK_N) =
        make_float4((inY1 & inX0) ? 1.f : 0.f, (inY1 & inX1) ? 1.f : 0.f,
                    (inY1 & inX2) ? 1.f : 0.f, (inY1 & inX3) ? 1.f : 0.f);
}

extern "C" void kernel_launch(void* const* d_in, const int* in_sizes, int n_in,
                              void* d_out, int out_size) {
    const float* boxes = (const float*)d_in[0];   // 256*4
    const float* pts   = (const float*)d_in[1];   // 256*32*2
    float* out = (float*)d_out;                   // 2 * 256*64*64
    const int B = in_sizes[0] / 4;                // 256
    float* bbox_out  = out;
    float* point_out = out + (size_t)B * MASK_N * MASK_N;
    dim3 grid(B, 2);
    zim_masks_kernel<<<grid, 256>>>(boxes, pts, bbox_out, point_out);
}

// round 5
// speedup vs baseline: 1.0269x; 1.0269x over previous
#include <cuda_runtime.h>
#include <cuda_bf16.h>

// Zim_67430986547716 — bbox mask + Gaussian point mask.
// R5: latency/occupancy-bound diagnosis (duration invariant to instruction
// mix, occ capped at 27.7 warps/SM by grid size).
//  1) Quadrant decomposition: grid (256,4), 32x32 px per block -> 8192 warps,
//     ~55 warps/SM resident.
//  2) exp-at-end: max_p exp(-d2_p/882) == exp(-(min_p d2_p)/882) (monotone),
//     so the hot loop is integer IADD3+IMNMX per pixel; exp once per pixel.
//     Invalid points get +0x40000000 on dy2 -> exp underflows to exactly 0.

#define MASK_N 64
#define NPTS   32
#define QDIM   32
#define INV_STRIDE (1.0f / 16.0f)
#define INV_2SIG2  (1.0f / 882.0f)   // 2*21*21

__global__ __launch_bounds__(256, 6)
void zim_masks_kernel(const float* __restrict__ boxes,
                      const float* __restrict__ pts,
                      float* __restrict__ bbox_out,
                      float* __restrict__ point_out)
{
    __shared__ int sdx2[NPTS * QDIM];   // 4KB: (j - px)^2 for this quadrant's cols
    __shared__ int sdy2[NPTS * QDIM];   // 4KB: (i - py)^2 + invalid_bias for rows
    __shared__ int spx[NPTS], spy[NPTS], sinv[NPTS];

    const int b      = blockIdx.x;
    const int quad   = blockIdx.y;              // 0..3
    const int i_base = (quad >> 1) << 5;        // 0 or 32
    const int j_base = (quad & 1) << 5;         // 0 or 32
    const int tid    = threadIdx.x;

    // ---- stage point centers + validity bias (one warp) ----
    if (tid < NPTS) {
        const float x = pts[(b * NPTS + tid) * 2 + 0];
        const float y = pts[(b * NPTS + tid) * 2 + 1];
        const int px = (int)floorf(x * INV_STRIDE);
        const int py = (int)floorf(y * INV_STRIDE);
        const bool valid = (px >= 0) & (py >= 0) & (px < MASK_N) & (py < MASK_N);
        spx[tid] = px;
        spy[tid] = py;
        sinv[tid] = valid ? 0 : 0x40000000;
    }

    // ---- bbox bounds (uniform; L1 broadcast) ----
    const float x0 = boxes[b * 4 + 0];
    const float y0 = boxes[b * 4 + 1];
    const float x1 = boxes[b * 4 + 2];
    const float y1 = boxes[b * 4 + 3];
    const int xmin_i = max((int)floorf(fminf(x0, x1) * INV_STRIDE), 0);
    const int ymin_i = max((int)floorf(fminf(y0, y1) * INV_STRIDE), 0);
    const int xmax_i = min((int)floorf(fmaxf(x0, x1) * INV_STRIDE) + 1, MASK_N);
    const int ymax_i = min((int)floorf(fmaxf(y0, y1) * INV_STRIDE) + 1, MASK_N);

    __syncthreads();

    // ---- integer distance tables (4 iters each, pure ALU) ----
    #pragma unroll
    for (int k = tid; k < NPTS * QDIM; k += 256) {
        const int p = k >> 5;
        const int d = j_base + (k & 31) - spx[p];
        sdx2[k] = d * d;
    }
    #pragma unroll
    for (int k = tid; k < NPTS * QDIM; k += 256) {
        const int p = k >> 5;
        const int d = i_base + (k & 31) - spy[p];
        sdy2[k] = d * d + sinv[p];
    }
    __syncthreads();

    // ---- per-thread: 1 row x 4 cols of the quadrant ----
    const int il = tid >> 3;           // 0..31 local row
    const int c  = (tid & 7) << 2;     // local col start 0,4,...,28

    int m0 = 0x7FFFFFFF, m1 = 0x7FFFFFFF, m2 = 0x7FFFFFFF, m3 = 0x7FFFFFFF;

    const int* dyp = &sdy2[il];
    const int* dxp = &sdx2[c];

    #pragma unroll 8
    for (int p = 0; p < NPTS; p++) {
        const int  dy2 = dyp[p * QDIM];
        const int4 dx  = *reinterpret_cast<const int4*>(dxp + p * QDIM);
        m0 = min(m0, dy2 + dx.x);
        m1 = min(m1, dy2 + dx.y);
        m2 = min(m2, dy2 + dx.z);
        m3 = min(m3, dy2 + dx.w);
    }

    // ---- one exp per pixel ----
    const float g0 = __expf((float)m0 * -INV_2SIG2);
    const float g1 = __expf((float)m1 * -INV_2SIG2);
    const float g2 = __expf((float)m2 * -INV_2SIG2);
    const float g3 = __expf((float)m3 * -INV_2SIG2);

    // ---- stores ----
    const int i = i_base + il;
    const int j = j_base + c;
    const size_t base = (size_t)b * (MASK_N * MASK_N) + (size_t)i * MASK_N + j;

    *reinterpret_cast<float4*>(point_out + base) = make_float4(g0, g1, g2, g3);

    const bool inY = (i >= ymin_i) & (i < ymax_i);
    float4 bv;
    bv.x = (inY & (j + 0 >= xmin_i) & (j + 0 < xmax_i)) ? 1.f : 0.f;
    bv.y = (inY & (j + 1 >= xmin_i) & (j + 1 < xmax_i)) ? 1.f : 0.f;
    bv.z = (inY & (j + 2 >= xmin_i) & (j + 2 < xmax_i)) ? 1.f : 0.f;
    bv.w = (inY & (j + 3 >= xmin_i) & (j + 3 < xmax_i)) ? 1.f : 0.f;
    *reinterpret_cast<float4*>(bbox_out + base) = bv;
}

extern "C" void kernel_launch(void* const* d_in, const int* in_sizes, int n_in,
                              void* d_out, int out_size) {
    const float* boxes = (const float*)d_in[0];   // 256*4
    const float* pts   = (const float*)d_in[1];   // 256*32*2
    float* out = (float*)d_out;                   // 2 * 256*64*64
    const int B = in_sizes[0] / 4;                // 256
    float* bbox_out  = out;
    float* point_out = out + (size_t)B * MASK_N * MASK_N;
    dim3 grid(B, 4);
    zim_masks_kernel<<<grid, 256>>>(boxes, pts, bbox_out, point_out);
}

// round 6
// speedup vs baseline: 1.2657x; 1.2325x over previous
#include <cuda_runtime.h>
#include <cuda_bf16.h>

// Zim_67430986547716 — bbox mask + Gaussian point mask.
// R6: L1/shared-wavefront bound (L1=51% while all pipes <25%). Switch the
// min-distance accumulation to u16 SIMD:
//   - dx^2 packed as u16 pairs (LDS.64), dy^2+bias duplicated in u32 (LDS.32)
//   - one __viaddmin_u16x2 per 2 pixels: min(m, dy2+dx2) fused, alu pipe
// Main loop: 4 issues / 12 shared bytes per 4 pixels (was 10 / 20).
// All quantities fit u16: d^2 <= 4096, invalid bias 30000, max sum 38192.
// exp at the end: max_p exp(-d2/882) == exp(-min_p d2 / 882) (monotone).

#define MASK_N 64
#define NPTS   32
#define QDIM   32
#define INV_STRIDE (1.0f / 16.0f)
#define INV_2SIG2  (1.0f / 882.0f)   // 2*21*21

__global__ __launch_bounds__(256, 6)
void zim_masks_kernel(const float* __restrict__ boxes,
                      const float* __restrict__ pts,
                      float* __restrict__ bbox_out,
                      float* __restrict__ point_out)
{
    __shared__ unsigned int sdx2p[NPTS * 16];  // 2KB: [p][cpair] = dx2(2c)|dx2(2c+1)<<16
    __shared__ unsigned int sdy2d[NPTS * 32];  // 4KB: [p][row]   = (dy2+bias) duplicated

    const int b      = blockIdx.x;
    const int quad   = blockIdx.y;              // 0..3
    const int i_base = (quad >> 1) << 5;        // 0 or 32
    const int j_base = (quad & 1) << 5;         // 0 or 32
    const int tid    = threadIdx.x;

    // ---- bbox bounds (uniform; L1 broadcast) ----
    const float x0 = boxes[b * 4 + 0];
    const float y0 = boxes[b * 4 + 1];
    const float x1 = boxes[b * 4 + 2];
    const float y1 = boxes[b * 4 + 3];
    const int xmin_i = max((int)floorf(fminf(x0, x1) * INV_STRIDE), 0);
    const int ymin_i = max((int)floorf(fminf(y0, y1) * INV_STRIDE), 0);
    const int xmax_i = min((int)floorf(fmaxf(x0, x1) * INV_STRIDE) + 1, MASK_N);
    const int ymax_i = min((int)floorf(fmaxf(y0, y1) * INV_STRIDE) + 1, MASK_N);

    // ---- build u16 distance tables directly from global pts (L1 broadcast) ----
    #pragma unroll
    for (int k = tid; k < NPTS * 16; k += 256) {        // 2 iters: dx2 pairs
        const int p = k >> 4;
        const float x = __ldg(&pts[(b * NPTS + p) * 2 + 0]);
        const int px = (int)floorf(x * INV_STRIDE);
        const int c0 = j_base + ((k & 15) << 1);
        const int d0 = c0 - px;
        const int d1 = c0 + 1 - px;
        sdx2p[k] = (unsigned int)(d0 * d0) | ((unsigned int)(d1 * d1) << 16);
    }
    #pragma unroll
    for (int k = tid; k < NPTS * 32; k += 256) {        // 4 iters: dy2+bias duplicated
        const int p = k >> 5;
        const float x = __ldg(&pts[(b * NPTS + p) * 2 + 0]);
        const float y = __ldg(&pts[(b * NPTS + p) * 2 + 1]);
        const int px = (int)floorf(x * INV_STRIDE);
        const int py = (int)floorf(y * INV_STRIDE);
        const bool valid = (px >= 0) & (py >= 0) & (px < MASK_N) & (py < MASK_N);
        const int d = i_base + (k & 31) - py;
        const unsigned int v = (unsigned int)(d * d + (valid ? 0 : 30000));
        sdy2d[k] = v | (v << 16);
    }
    __syncthreads();

    // ---- per-thread: 1 row x 4 cols of the quadrant, u16x2 SIMD min ----
    const int il = tid >> 3;            // 0..31 local row
    const int cg = (tid & 7);           // col group: cols 4*cg .. 4*cg+3

    unsigned int m01 = 0xFFFFFFFFu, m23 = 0xFFFFFFFFu;

    const unsigned int* dyp = &sdy2d[il];
    const unsigned int* dxp = &sdx2p[cg * 2];

    #pragma unroll 8
    for (int p = 0; p < NPTS; p++) {
        const unsigned int dyd = dyp[p * 32];
        const uint2 dx = *reinterpret_cast<const uint2*>(dxp + p * 16);
        m01 = __viaddmin_u16x2(dyd, dx.x, m01);
        m23 = __viaddmin_u16x2(dyd, dx.y, m23);
    }

    // ---- unpack + one exp per pixel ----
    const float g0 = __expf((float)(m01 & 0xFFFFu) * -INV_2SIG2);
    const float g1 = __expf((float)(m01 >> 16)     * -INV_2SIG2);
    const float g2 = __expf((float)(m23 & 0xFFFFu) * -INV_2SIG2);
    const float g3 = __expf((float)(m23 >> 16)     * -INV_2SIG2);

    // ---- stores ----
    const int i = i_base + il;
    const int j = j_base + (cg << 2);
    const size_t base = (size_t)b * (MASK_N * MASK_N) + (size_t)i * MASK_N + j;

    *reinterpret_cast<float4*>(point_out + base) = make_float4(g0, g1, g2, g3);

    const bool inY = (i >= ymin_i) & (i < ymax_i);
    float4 bv;
    bv.x = (inY & (j + 0 >= xmin_i) & (j + 0 < xmax_i)) ? 1.f : 0.f;
    bv.y = (inY & (j + 1 >= xmin_i) & (j + 1 < xmax_i)) ? 1.f : 0.f;
    bv.z = (inY & (j + 2 >= xmin_i) & (j + 2 < xmax_i)) ? 1.f : 0.f;
    bv.w = (inY & (j + 3 >= xmin_i) & (j + 3 < xmax_i)) ? 1.f : 0.f;
    *reinterpret_cast<float4*>(bbox_out + base) = bv;
}

extern "C" void kernel_launch(void* const* d_in, const int* in_sizes, int n_in,
                              void* d_out, int out_size) {
    const float* boxes = (const float*)d_in[0];   // 256*4
    const float* pts   = (const float*)d_in[1];   // 256*32*2
    float* out = (float*)d_out;                   // 2 * 256*64*64
    const int B = in_sizes[0] / 4;                // 256
    float* bbox_out  = out;
    float* point_out = out + (size_t)B * MASK_N * MASK_N;
    dim3 grid(B, 4);
    zim_masks_kernel<<<grid, 256>>>(boxes, pts, bbox_out, point_out);
}